// round 10
// baseline (speedup 1.0000x reference)
#include <cuda_runtime.h>
#include <cstring>
#include <cfloat>
#include <cmath>

// Problem shape: activations [B=64, C=256, L=512] float32.
#define C_DIM 256
#define B_DIM 64
#define L_DIM 512
#define N_PER_C (B_DIM * L_DIM)               // 32768 per channel
#define F4_PER_ROW (L_DIM / 4)                // 128
#define F4_PER_C (N_PER_C / 4)                // 8192
#define TOTAL_F4 (B_DIM * C_DIM * L_DIM / 4)  // 2097152

#define NB 2048                                // bucket count
#define BSCALE 1638.4f                         // NB / 1.25

#define LIF_BLOCKS 1024
#define LIF_CHUNKS 8                           // 1024*256*8 == TOTAL_F4

// Per-channel affine coefficients: y = x * g_scale[c] + g_shift[c]
__device__ float g_scale[C_DIM];
__device__ float g_shift[C_DIM];

// Bucket table in global, staged by bn_stats block 0, loaded to smem per block.
__device__ float2 g_tab[NB];

struct BucketTab { float2 b[NB]; };   // 16 KB by-value kernel param
struct LifTab    { float e[64]; float v[64]; };

// ---------------------------------------------------------------------------
// Kernel 1: per-channel mean/var -> scale & shift, with explicit MLP=8 load
// batches (R9 showed regs=32 / MLP~2 / 2.3 TB/s latency-bound at occ 21%).
// Block 0 additionally stages the bucket table to global.
// ---------------------------------------------------------------------------
__global__ void __launch_bounds__(256) bn_stats_kernel(
    const float* __restrict__ act,
    const float* __restrict__ w,
    const float* __restrict__ bias,
    const BucketTab tab)
{
    const int c = blockIdx.x;
    const int tid = threadIdx.x;
    const float4* a4 = (const float4*)act;

    // Stage bucket table (block 0 only): 2048 float2 by 256 threads.
    if (c == 0) {
        #pragma unroll
        for (int u = 0; u < NB / 256; ++u)
            g_tab[u * 256 + tid] = tab.b[u * 256 + tid];
    }

    float s0 = 0.f, s1 = 0.f, s2 = 0.f, s3 = 0.f;
    float q0 = 0.f, q1 = 0.f, q2 = 0.f, q3 = 0.f;

    // 32 float4 per thread, as 4 batches of 8 explicit loads (MLP=8).
    #pragma unroll
    for (int kb = 0; kb < 4; ++kb) {
        float4 r[8];
        #pragma unroll
        for (int u = 0; u < 8; ++u) {
            const int j = (kb * 8 + u) * 256 + tid;    // 0..8191
            const int bb  = j >> 7;
            const int pos = j & 127;
            r[u] = a4[bb * (C_DIM * F4_PER_ROW) + c * F4_PER_ROW + pos];
        }
        #pragma unroll
        for (int u = 0; u < 8; ++u) {
            s0 += r[u].x; s1 += r[u].y; s2 += r[u].z; s3 += r[u].w;
            q0 = fmaf(r[u].x, r[u].x, q0);
            q1 = fmaf(r[u].y, r[u].y, q1);
            q2 = fmaf(r[u].z, r[u].z, q2);
            q3 = fmaf(r[u].w, r[u].w, q3);
        }
    }

    double s = (double)s0 + (double)s1 + (double)s2 + (double)s3;
    double q = (double)q0 + (double)q1 + (double)q2 + (double)q3;

    __shared__ double sh_s[256];
    __shared__ double sh_q[256];
    sh_s[tid] = s;
    sh_q[tid] = q;
    __syncthreads();

    #pragma unroll
    for (int off = 128; off > 0; off >>= 1) {
        if (tid < off) {
            sh_s[tid] += sh_s[tid + off];
            sh_q[tid] += sh_q[tid + off];
        }
        __syncthreads();
    }

    if (tid == 0) {
        const double inv_n = 1.0 / (double)N_PER_C;
        double mean = sh_s[0] * inv_n;
        double var  = sh_q[0] * inv_n - mean * mean;
        double scale = (double)w[c] * rsqrt(var + 1e-5);
        g_scale[c] = (float)scale;
        g_shift[c] = (float)((double)bias[c] - mean * scale);
    }
}

// ---------------------------------------------------------------------------
// Kernel 2a (fast path, R9-verified ~9.5us): direct-mapped float2 bucket
// lookup, grid-stride. bucket = (edge, packed{v_hi hi16, v_lo lo16} bf16);
// value = (a > edge) ? v_hi : v_lo ; result sign = sign(x).
// ---------------------------------------------------------------------------
__global__ void __launch_bounds__(256) lif_bucket_kernel(
    const float* __restrict__ act,
    float* __restrict__ out)
{
    __shared__ float2 sb[NB];
    for (int i = threadIdx.x; i < NB; i += 256)
        sb[i] = g_tab[i];                       // coalesced LDG
    __syncthreads();

    const int base = blockIdx.x * 256 + threadIdx.x;

    #pragma unroll
    for (int chunk = 0; chunk < LIF_CHUNKS; ++chunk) {
        const int i = base + chunk * (LIF_BLOCKS * 256);  // float4 index
        const int c = (i >> 7) & (C_DIM - 1);

        const float sc = g_scale[c];
        const float sh = g_shift[c];

        float4 v = ((const float4*)act)[i];
        float xs[4] = { fmaf(v.x, sc, sh), fmaf(v.y, sc, sh),
                        fmaf(v.z, sc, sh), fmaf(v.w, sc, sh) };
        float r[4];

        #pragma unroll
        for (int k = 0; k < 4; ++k) {
            const float a = fabsf(xs[k]);
            int idx = (int)(a * BSCALE);
            idx = min(idx, NB - 1);
            const float2 bk = sb[idx];
            const unsigned pv = __float_as_uint(bk.y);
            const unsigned sel = (a > bk.x) ? (pv & 0xFFFF0000u) : (pv << 16);
            r[k] = __uint_as_float(sel |
                      (__float_as_uint(xs[k]) & 0x80000000u));
        }

        ((float4*)out)[i] = make_float4(r[0], r[1], r[2], r[3]);
    }
}

// ---------------------------------------------------------------------------
// Kernel 2b (fallback, R5-verified): 64-entry binary-search LUT.
// ---------------------------------------------------------------------------
__global__ void __launch_bounds__(256) lif_lut_kernel(
    const float* __restrict__ act,
    float* __restrict__ out,
    const LifTab tab)
{
    __shared__ float se[64];
    __shared__ float sv[64];
    if (threadIdx.x < 64) {
        se[threadIdx.x] = tab.e[threadIdx.x];
        sv[threadIdx.x] = tab.v[threadIdx.x];
    }
    __syncthreads();

    const int i = blockIdx.x * 256 + threadIdx.x;
    const int c = (i >> 7) & (C_DIM - 1);
    const float sc = g_scale[c];
    const float sh = g_shift[c];

    float4 v = ((const float4*)act)[i];
    float xs[4] = { fmaf(v.x, sc, sh), fmaf(v.y, sc, sh),
                    fmaf(v.z, sc, sh), fmaf(v.w, sc, sh) };
    float r[4];

    #pragma unroll
    for (int k = 0; k < 4; ++k) {
        const float a = fabsf(xs[k]);
        int pos = 0;
        #pragma unroll
        for (int s = 32; s > 0; s >>= 1)
            if (se[pos + s - 1] < a) pos += s;
        r[k] = __uint_as_float(__float_as_uint(sv[pos]) |
                               (__float_as_uint(xs[k]) & 0x80000000u));
    }

    ((float4*)out)[i] = make_float4(r[0], r[1], r[2], r[3]);
}

// ---------------------------------------------------------------------------
// Kernel 2c (last resort, R2-verified): direct 16-step scan.
// ---------------------------------------------------------------------------
__device__ __forceinline__ float lif16(float x)
{
    float mem = x;
    float sgn = __int_as_float((__float_as_int(mem) & 0x80000000) | 0x3f800000);
    float spk = (fabsf(mem) > 1.0f) ? sgn : 0.0f;
    float sum = spk;
    #pragma unroll
    for (int t = 1; t < 16; ++t) {
        mem = fmaf(0.9f, mem, x - spk);
        sgn = __int_as_float((__float_as_int(mem) & 0x80000000) | 0x3f800000);
        spk = (fabsf(mem) > 1.0f) ? sgn : 0.0f;
        sum += spk;
    }
    return sum * 0.0625f;
}

__global__ void __launch_bounds__(256) lif_kernel(
    const float* __restrict__ act,
    float* __restrict__ out)
{
    const int i = blockIdx.x * 256 + threadIdx.x;
    const int c = (i >> 7) & (C_DIM - 1);
    const float sc = g_scale[c];
    const float sh = g_shift[c];
    float4 v = ((const float4*)act)[i];
    float4 r;
    r.x = lif16(fmaf(v.x, sc, sh));
    r.y = lif16(fmaf(v.y, sc, sh));
    r.z = lif16(fmaf(v.z, sc, sh));
    r.w = lif16(fmaf(v.w, sc, sh));
    ((float4*)out)[i] = r;
}

// ===========================================================================
// Host-side machinery.
// ===========================================================================
static float host_lif16(float x)
{
    float mem = x;
    float spk = (fabsf(mem) > 1.0f) ? copysignf(1.0f, mem) : 0.0f;
    float sum = spk;
    for (int t = 1; t < 16; ++t) {
        mem = fmaf(0.9f, mem, x - spk);
        spk = (fabsf(mem) > 1.0f) ? copysignf(1.0f, mem) : 0.0f;
        sum += spk;
    }
    return sum * 0.0625f;
}

static inline unsigned f2u(float f) { unsigned u; std::memcpy(&u, &f, 4); return u; }
static inline float u2f(unsigned u) { float f; std::memcpy(&f, &u, 4); return f; }

static float host_bisect_edge(float lo, float hi, float vlo)
{
    for (int it = 0; it < 64; ++it) {
        unsigned a = f2u(lo), b = f2u(hi);
        if (b - a <= 1u) break;
        float m = u2f(a + (b - a) / 2u);
        if (host_lif16(m) == vlo) lo = m; else hi = m;
    }
    return lo;
}

// Enumerate edges/vals of the piecewise-constant f(|x|).
static int host_find_edges(float* edges, float* vals, int maxK)
{
    int K = 0;
    float cur = host_lif16(0.0f);
    float px = 0.0f;
    vals[0] = cur;
    bool overflow = false;

    auto feed = [&](float x) {
        float fv = host_lif16(x);
        if (fv != cur) {
            if (K < maxK) {
                edges[K] = host_bisect_edge(px, x, cur);
                ++K;
                vals[K] = fv;
            } else overflow = true;
            cur = fv;
        }
        px = x;
    };

    const int N1 = 1 << 20;
    for (int j = 1; j <= N1; ++j)
        feed(1.25f * ((float)j * (1.0f / (float)N1)));
    for (int j = 1; j <= 15104; ++j)
        feed(1.25f + (float)j * 0.0009765625f);

    return overflow ? -1 : K;
}

// Exact replica of device bucket index arithmetic (fp32 mul, truncate).
static inline int host_bidx(float a)
{
    float p = a * BSCALE;          // single-precision rn multiply
    int idx = (int)p;              // truncation == device F2I.rz
    return idx > NB - 1 ? NB - 1 : idx;
}

static float host_bucket_eval(const BucketTab& bt, float a)
{
    const float2& b = bt.b[host_bidx(a)];
    unsigned pv = f2u(b.y);
    unsigned sel = (a > b.x) ? (pv & 0xFFFF0000u) : (pv << 16);
    return u2f(sel);
}

// Build + validate bucket table (<=1 edge per bucket; bf16-exact values).
static bool host_build_buckets(BucketTab& bt,
                               const float* edges, const float* vals, int K)
{
    int i = 0;
    for (int j = 0; j < NB; ++j) {
        if (i < K && host_bidx(edges[i]) < j) return false;
        int i0 = i, cnt = 0;
        while (i < K && host_bidx(edges[i]) == j) { ++cnt; ++i; }
        if (cnt > 1) return false;

        float e = FLT_MAX;
        float vlo = vals[i0], vhi = vals[i0];
        if (cnt == 1) { e = edges[i0]; vhi = vals[i0 + 1]; }

        unsigned ulo = f2u(vlo), uhi = f2u(vhi);
        if ((ulo & 0xFFFFu) || (uhi & 0xFFFFu)) return false; // not bf16-exact
        float2 b;
        b.x = e;
        b.y = u2f((uhi & 0xFFFF0000u) | (ulo >> 16));
        bt.b[j] = b;
    }
    if (i != K) return false;

    auto chk = [&](float a) -> bool {
        float ref = host_lif16(a);
        return ref >= 0.0f && host_bucket_eval(bt, a) == ref;
    };
    // Strong checks: every edge +/-1 ulp, every bucket boundary +/-1 ulp.
    for (int k = 0; k < K; ++k) {
        float e = edges[k];
        if (!chk(e)) return false;
        if (!chk(u2f(f2u(e) + 1u))) return false;
        if (f2u(e) > 0 && !chk(u2f(f2u(e) - 1u))) return false;
    }
    for (int j = 1; j < NB; ++j) {
        float bnd = (float)j * (1.25f / (float)NB);
        if (!chk(bnd)) return false;
        if (!chk(u2f(f2u(bnd) + 1u))) return false;
        if (!chk(u2f(f2u(bnd) - 1u))) return false;
    }
    // Interior grid (2^18: ~600x finer than min inter-edge gap).
    const int NV = 1 << 18;
    for (int j = 0; j <= NV; ++j)
        if (!chk(1.25f * ((float)j * (1.0f / (float)NV)))) return false;
    for (int j = 1; j <= 2048; ++j)
        if (!chk(1.25f + (float)j * 0.0073242187f)) return false;
    return true;
}

static float host_lut_eval(const LifTab& tab, float a)
{
    int pos = 0;
    for (int s = 32; s > 0; s >>= 1)
        if (tab.e[pos + s - 1] < a) pos += s;
    return tab.v[pos];
}

static bool host_build_lut(LifTab& tab,
                           const float* edges, const float* vals, int K)
{
    if (K > 63) return false;
    for (int i2 = K; i2 < 64; ++i2) tab.e[i2] = FLT_MAX;
    for (int i2 = 0; i2 < K; ++i2)  tab.e[i2] = edges[i2];
    for (int i2 = 0; i2 <= K; ++i2) tab.v[i2] = vals[i2];
    for (int i2 = K + 1; i2 < 64; ++i2) tab.v[i2] = vals[K];

    for (int i2 = 0; i2 < K; ++i2) {
        float e = tab.e[i2];
        float eu = u2f(f2u(e) + 1u);
        if (host_lut_eval(tab, e)  != host_lif16(e))  return false;
        if (host_lut_eval(tab, eu) != host_lif16(eu)) return false;
    }
    for (int j = 0; j <= 4096; ++j) {
        float x = 1.25f * ((float)j / 4096.0f);
        if (host_lut_eval(tab, x) != host_lif16(x)) return false;
    }
    return true;
}

// ---------------------------------------------------------------------------
// Launch. Inputs (metadata order): activations, bn_weight, bn_bias.
// ---------------------------------------------------------------------------
extern "C" void kernel_launch(void* const* d_in, const int* in_sizes, int n_in,
                              void* d_out, int out_size)
{
    const float* act  = (const float*)d_in[0];
    const float* w    = (const float*)d_in[1];
    const float* bias = (const float*)d_in[2];
    float* out = (float*)d_out;

    static float edges[96], vals[97];
    int K = host_find_edges(edges, vals, 90);

    static BucketTab btab;                      // 16 KB; static: off stack
    bool bucket_ok = (K >= 0) && host_build_buckets(btab, edges, vals, K);
    LifTab ltab;
    bool lut_ok = (K >= 0) && host_build_lut(ltab, edges, vals, K);

    if (!bucket_ok)
        std::memset(&btab, 0, sizeof(btab));    // staged but unused

    bn_stats_kernel<<<C_DIM, 256>>>(act, w, bias, btab);

    if (bucket_ok)
        lif_bucket_kernel<<<LIF_BLOCKS, 256>>>(act, out);
    else if (lut_ok)
        lif_lut_kernel<<<TOTAL_F4 / 256, 256>>>(act, out, ltab);
    else
        lif_kernel<<<TOTAL_F4 / 256, 256>>>(act, out);
}